// round 9
// baseline (speedup 1.0000x reference)
#include <cuda_runtime.h>
#include <math.h>
#include <stdint.h>

#define S_LEN 2048
#define E_DIM 1024
#define H_DIM 1024
#define V_DIM 32000
#define EH    2048   // E+H
#define NBLK  148
#define NTHR  512
#define NWARP 16

// ---------------- scratch (no allocations allowed) ----------------
__device__ float d_gates[4 * H_DIM];
__device__ float d_h[H_DIM];
__device__ float d_t[H_DIM];
__device__ float d_scores[S_LEN];
__device__ float d_ctx[E_DIM];
__device__ float d_xt[H_DIM];
__device__ float d_logits[V_DIM];
__device__ float d_sumexp;
__device__ float d_smax, d_sinv;
__device__ unsigned d_barcnt;
__device__ unsigned d_exitcnt;

__device__ __forceinline__ float sigmoidf(float x) { return 1.0f / (1.0f + expf(-x)); }

__device__ __forceinline__ uint32_t f2tf32(float x) {
    uint32_t u;
    asm("cvt.rna.tf32.f32 %0, %1;" : "=r"(u) : "f"(x));
    return u;
}

__device__ __forceinline__ void mma_tf32(float* c, const uint32_t* a, const uint32_t* b) {
    asm volatile(
        "mma.sync.aligned.m16n8k8.row.col.f32.tf32.tf32.f32 "
        "{%0,%1,%2,%3}, {%4,%5,%6,%7}, {%8,%9}, {%0,%1,%2,%3};"
        : "+f"(c[0]), "+f"(c[1]), "+f"(c[2]), "+f"(c[3])
        : "r"(a[0]), "r"(a[1]), "r"(a[2]), "r"(a[3]), "r"(b[0]), "r"(b[1]));
}

// grid barrier: all 148 CTAs are co-resident (grid == #SMs, 1 CTA/SM), so
// atomic-counter spin is deadlock-free. target = step * NBLK, monotonic per launch.
__device__ __forceinline__ void gridbar(unsigned target) {
    __syncthreads();
    if (threadIdx.x == 0) {
        __threadfence();
        atomicAdd(&d_barcnt, 1u);
        while (*(volatile unsigned*)&d_barcnt < target) { }
        __threadfence();
    }
    __syncthreads();
}

struct SMem {
    union {
        float vec[EH + H_DIM];               // gates: [lstm_in | h_prev]; also sh / cat / sx
        struct {
            uint32_t As[128][36];
            uint32_t Bs[128][36];
            float    srow[4][128];
        } sc;
    } u;
    float wred[NWARP];
    float stat2[2];
};

__global__ __launch_bounds__(NTHR, 1)
void decoder_kernel(const float* __restrict__ enc,
                    const int*   __restrict__ word_input,
                    const float* __restrict__ last_ctx,
                    const float* __restrict__ h0,
                    const float* __restrict__ c0,
                    const float* __restrict__ emb,
                    const float* __restrict__ W_ih, const float* __restrict__ b_ih,
                    const float* __restrict__ W_hh, const float* __restrict__ b_hh,
                    const float* __restrict__ W_att, const float* __restrict__ b_att,
                    const float* __restrict__ v,
                    const float* __restrict__ W_ah, const float* __restrict__ b_ah,
                    const float* __restrict__ W_out, const float* __restrict__ b_out,
                    float* __restrict__ out,
                    float* out_h, float* out_c, float* out_xt, float* out_w)
{
    __shared__ SMem sm;
    const int tid  = threadIdx.x;
    const int blk  = blockIdx.x;
    const int warp = tid >> 5, lane = tid & 31;

    // ================= phase 1: LSTM gate rows =================
    {
        int word = word_input[0];
        for (int i = tid; i < EH + H_DIM; i += NTHR)
            sm.u.vec[i] = (i < H_DIM) ? last_ctx[i]
                        : (i < EH)    ? emb[(size_t)word * E_DIM + (i - H_DIM)]
                                      : h0[i - EH];
        __syncthreads();
        for (int r = blk * NWARP + warp; r < 4 * H_DIM; r += NBLK * NWARP) {
            const float* wrow = W_ih + (size_t)r * EH;
            float acc = 0.f;
            #pragma unroll
            for (int k = lane * 4; k < EH; k += 128) {
                float4 w4 = *(const float4*)&wrow[k];
                float4 x4 = *(const float4*)&sm.u.vec[k];
                acc += w4.x*x4.x + w4.y*x4.y + w4.z*x4.z + w4.w*x4.w;
            }
            const float* hrow = W_hh + (size_t)r * H_DIM;
            #pragma unroll
            for (int k = lane * 4; k < H_DIM; k += 128) {
                float4 w4 = *(const float4*)&hrow[k];
                float4 x4 = *(const float4*)&sm.u.vec[EH + k];
                acc += w4.x*x4.x + w4.y*x4.y + w4.z*x4.z + w4.w*x4.w;
            }
            #pragma unroll
            for (int off = 16; off; off >>= 1) acc += __shfl_down_sync(0xffffffffu, acc, off);
            if (lane == 0) d_gates[r] = acc + b_ih[r] + b_hh[r];
        }
    }
    gridbar(1 * NBLK);

    // ================= phase 2: h,c + zero scratch + t = W_att[:,:H].h + b_att =================
    {
        for (int j = tid; j < H_DIM; j += NTHR) {
            float iv = sigmoidf(d_gates[j]);
            float fv = sigmoidf(d_gates[j +   H_DIM]);
            float gv = tanhf  (d_gates[j + 2*H_DIM]);
            float ov = sigmoidf(d_gates[j + 3*H_DIM]);
            float cv = fv * c0[j] + iv * gv;
            float hv = ov * tanhf(cv);
            sm.u.vec[j] = hv;     // sh
            if (blk == 0) {
                d_h[j] = hv;
                if (out_h) out_h[j] = hv;
                if (out_c) out_c[j] = cv;
            }
        }
        if (blk == 1) for (int i = tid; i < S_LEN; i += NTHR) d_scores[i] = 0.f;
        if (blk == 2) for (int i = tid; i < E_DIM; i += NTHR) d_ctx[i] = 0.f;
        if (blk == 3 && tid == 0) d_sumexp = 0.f;
        __syncthreads();

        int r = warp * NBLK + blk;
        if (r < H_DIM) {
            const float* row = W_att + (size_t)r * EH;
            float acc = 0.f;
            #pragma unroll
            for (int k = lane * 4; k < H_DIM; k += 128) {
                float4 w4 = *(const float4*)&row[k];
                float4 x4 = *(const float4*)&sm.u.vec[k];
                acc += w4.x*x4.x + w4.y*x4.y + w4.z*x4.z + w4.w*x4.w;
            }
            #pragma unroll
            for (int off = 16; off; off >>= 1) acc += __shfl_down_sync(0xffffffffu, acc, off);
            if (lane == 0) d_t[r] = acc + b_att[r];
        }
    }
    gridbar(2 * NBLK);

    // ================= phase 3: scores GEMM (tf32 mma), 128 blocks of 128x128 =================
    if (blk < 128) {
        const int m0 = (blk >> 3) * 128;     // 16 m-tiles
        const int n0 = (blk & 7) * 128;      // 8 n-tiles
        const int g = lane >> 2, tg = lane & 3;
        const int wm = (warp >> 2) * 32;     // 4 warp-rows
        const int wn = (warp & 3) * 32;      // 4 warp-cols

        float c[2][4][4];
        #pragma unroll
        for (int mt = 0; mt < 2; mt++)
            #pragma unroll
            for (int nt = 0; nt < 4; nt++)
                #pragma unroll
                for (int i = 0; i < 4; i++) c[mt][nt][i] = 0.f;

        const int lr = tid >> 2;             // 0..127
        const int lc = (tid & 3) * 8;        // 0,8,16,24
        const float* aptr = enc   + (size_t)(m0 + lr) * E_DIM + lc;
        const float* bptr = W_att + (size_t)(n0 + lr) * EH + H_DIM + lc;

        float4 ra0 = *(const float4*)aptr, ra1 = *(const float4*)(aptr + 4);
        float4 rb0 = *(const float4*)bptr, rb1 = *(const float4*)(bptr + 4);

        for (int kt = 0; kt < E_DIM / 32; kt++) {
            sm.u.sc.As[lr][lc+0]=f2tf32(ra0.x); sm.u.sc.As[lr][lc+1]=f2tf32(ra0.y);
            sm.u.sc.As[lr][lc+2]=f2tf32(ra0.z); sm.u.sc.As[lr][lc+3]=f2tf32(ra0.w);
            sm.u.sc.As[lr][lc+4]=f2tf32(ra1.x); sm.u.sc.As[lr][lc+5]=f2tf32(ra1.y);
            sm.u.sc.As[lr][lc+6]=f2tf32(ra1.z); sm.u.sc.As[lr][lc+7]=f2tf32(ra1.w);
            sm.u.sc.Bs[lr][lc+0]=f2tf32(rb0.x); sm.u.sc.Bs[lr][lc+1]=f2tf32(rb0.y);
            sm.u.sc.Bs[lr][lc+2]=f2tf32(rb0.z); sm.u.sc.Bs[lr][lc+3]=f2tf32(rb0.w);
            sm.u.sc.Bs[lr][lc+4]=f2tf32(rb1.x); sm.u.sc.Bs[lr][lc+5]=f2tf32(rb1.y);
            sm.u.sc.Bs[lr][lc+6]=f2tf32(rb1.z); sm.u.sc.Bs[lr][lc+7]=f2tf32(rb1.w);
            __syncthreads();

            if (kt + 1 < E_DIM / 32) {
                const float* an = aptr + (size_t)(kt + 1) * 32;
                const float* bn = bptr + (size_t)(kt + 1) * 32;
                ra0 = *(const float4*)an; ra1 = *(const float4*)(an + 4);
                rb0 = *(const float4*)bn; rb1 = *(const float4*)(bn + 4);
            }

            #pragma unroll
            for (int ks = 0; ks < 4; ks++) {
                int k0 = ks * 8;
                uint32_t a[2][4], b[4][2];
                #pragma unroll
                for (int mt = 0; mt < 2; mt++) {
                    int r = wm + mt * 16 + g;
                    a[mt][0] = sm.u.sc.As[r    ][k0 + tg    ];
                    a[mt][1] = sm.u.sc.As[r + 8][k0 + tg    ];
                    a[mt][2] = sm.u.sc.As[r    ][k0 + tg + 4];
                    a[mt][3] = sm.u.sc.As[r + 8][k0 + tg + 4];
                }
                #pragma unroll
                for (int nt = 0; nt < 4; nt++) {
                    int r = wn + nt * 8 + g;
                    b[nt][0] = sm.u.sc.Bs[r][k0 + tg    ];
                    b[nt][1] = sm.u.sc.Bs[r][k0 + tg + 4];
                }
                #pragma unroll
                for (int mt = 0; mt < 2; mt++)
                    #pragma unroll
                    for (int nt = 0; nt < 4; nt++)
                        mma_tf32(c[mt][nt], a[mt], b[nt]);
            }
            __syncthreads();
        }

        // epilogue: v . tanh(acc + t), fold over this block's 128 n-cols
        #pragma unroll
        for (int mt = 0; mt < 2; mt++) {
            float p0 = 0.f, p1 = 0.f;
            #pragma unroll
            for (int nt = 0; nt < 4; nt++) {
                #pragma unroll
                for (int cc = 0; cc < 2; cc++) {
                    int n = n0 + wn + nt * 8 + tg * 2 + cc;
                    float tn = d_t[n];
                    float vn = v[n];
                    p0 += vn * tanhf(c[mt][nt][cc]     + tn);
                    p1 += vn * tanhf(c[mt][nt][2 + cc] + tn);
                }
            }
            p0 += __shfl_xor_sync(0xffffffffu, p0, 1);
            p0 += __shfl_xor_sync(0xffffffffu, p0, 2);
            p1 += __shfl_xor_sync(0xffffffffu, p1, 1);
            p1 += __shfl_xor_sync(0xffffffffu, p1, 2);
            if (tg == 0) {
                sm.u.sc.srow[warp & 3][wm + mt * 16 + g    ] = p0;
                sm.u.sc.srow[warp & 3][wm + mt * 16 + g + 8] = p1;
            }
        }
        __syncthreads();
        if (tid < 128)
            atomicAdd(&d_scores[m0 + tid],
                      (sm.u.sc.srow[0][tid] + sm.u.sc.srow[1][tid]) +
                      (sm.u.sc.srow[2][tid] + sm.u.sc.srow[3][tid]));
    }
    gridbar(3 * NBLK);

    // ================= phase 4: softmax stats (block 0) =================
    if (blk == 0) {
        float m = -1e30f;
        #pragma unroll
        for (int i = tid; i < S_LEN; i += NTHR) m = fmaxf(m, d_scores[i]);
        #pragma unroll
        for (int off = 16; off; off >>= 1) m = fmaxf(m, __shfl_xor_sync(0xffffffffu, m, off));
        if (lane == 0) sm.wred[warp] = m;
        __syncthreads();
        float mx;
        {
            float t0 = sm.wred[0];
            #pragma unroll
            for (int i = 1; i < NWARP; i++) t0 = fmaxf(t0, sm.wred[i]);
            mx = t0;
        }
        float s = 0.f;
        #pragma unroll
        for (int i = tid; i < S_LEN; i += NTHR) s += expf(d_scores[i] - mx);
        #pragma unroll
        for (int off = 16; off; off >>= 1) s += __shfl_xor_sync(0xffffffffu, s, off);
        __syncthreads();
        if (lane == 0) sm.wred[warp] = s;
        __syncthreads();
        if (tid == 0) {
            float ss = sm.wred[0];
            #pragma unroll
            for (int i = 1; i < NWARP; i++) ss += sm.wred[i];
            d_smax = mx;
            d_sinv = 1.0f / ss;
        }
    }
    gridbar(4 * NBLK);

    // ================= phase 5: context = softmax(scores) @ enc =================
    if (blk < 128) {
        float mx = d_smax, inv = d_sinv;
        int s0 = blk * 16;
        if (tid < 16) {
            float w = expf(d_scores[s0 + tid] - mx) * inv;
            sm.u.vec[tid] = w;
            if (out_w) out_w[s0 + tid] = w;
        }
        __syncthreads();
        int e = tid * 2;
        float a0 = 0.f, a1 = 0.f;
        #pragma unroll
        for (int s = 0; s < 16; s++) {
            float w = sm.u.vec[s];
            float2 x = *(const float2*)&enc[(size_t)(s0 + s) * E_DIM + e];
            a0 += w * x.x;
            a1 += w * x.y;
        }
        atomicAdd(&d_ctx[e],     a0);
        atomicAdd(&d_ctx[e + 1], a1);
    }
    gridbar(5 * NBLK);

    // ================= phase 6: x_t = tanh(W_ah @ [ctx; h] + b_ah) =================
    {
        for (int i = tid; i < EH; i += NTHR)
            sm.u.vec[i] = (i < H_DIM) ? d_ctx[i] : d_h[i - H_DIM];
        __syncthreads();
        int r = warp * NBLK + blk;
        if (r < H_DIM) {
            const float* row = W_ah + (size_t)r * EH;
            float acc = 0.f;
            #pragma unroll
            for (int k = lane * 4; k < EH; k += 128) {
                float4 w4 = *(const float4*)&row[k];
                float4 x4 = *(const float4*)&sm.u.vec[k];
                acc += w4.x*x4.x + w4.y*x4.y + w4.z*x4.z + w4.w*x4.w;
            }
            #pragma unroll
            for (int off = 16; off; off >>= 1) acc += __shfl_down_sync(0xffffffffu, acc, off);
            if (lane == 0) {
                float x = tanhf(acc + b_ah[r]);
                d_xt[r] = x;
                if (out_xt) out_xt[r] = x;
            }
        }
    }
    gridbar(6 * NBLK);

    // ================= phase 7: logits = W_out @ x_t + b_out, fused sumexp =================
    {
        for (int i = tid; i < H_DIM; i += NTHR) sm.u.vec[i] = d_xt[i];
        __syncthreads();
        float esum = 0.f;
        for (int r = blk * NWARP + warp; r < V_DIM; r += NBLK * NWARP) {
            const float* wr = W_out + (size_t)r * H_DIM;
            float acc = 0.f;
            #pragma unroll
            for (int k = lane * 4; k < H_DIM; k += 128) {
                float4 w4 = *(const float4*)&wr[k];
                float4 x4 = *(const float4*)&sm.u.vec[k];
                acc += w4.x*x4.x + w4.y*x4.y + w4.z*x4.z + w4.w*x4.w;
            }
            #pragma unroll
            for (int off = 16; off; off >>= 1) acc += __shfl_down_sync(0xffffffffu, acc, off);
            if (lane == 0) {
                float lg = acc + b_out[r];
                d_logits[r] = lg;
                esum += expf(lg);    // logits are O(1): exp without max is safe
            }
        }
        if (lane == 0) sm.wred[warp] = esum;
        __syncthreads();
        if (tid == 0) {
            float s = 0.f;
            #pragma unroll
            for (int i = 0; i < NWARP; i++) s += sm.wred[i];
            atomicAdd(&d_sumexp, s);
        }
    }
    gridbar(7 * NBLK);

    // ================= phase 8: writeout =================
    {
        float lse = logf(d_sumexp);
        for (int i = blk * NTHR + tid; i < V_DIM; i += NBLK * NTHR)
            out[i] = d_logits[i] - lse;
    }

    // exit protocol: last block to finish resets barrier counters for next replay
    __syncthreads();
    if (tid == 0) {
        __threadfence();
        unsigned n = atomicAdd(&d_exitcnt, 1u);
        if (n == NBLK - 1) {
            d_barcnt  = 0u;
            d_exitcnt = 0u;
            __threadfence();
        }
    }
}

// ---------------- launch ----------------
extern "C" void kernel_launch(void* const* d_in, const int* in_sizes, int n_in,
                              void* d_out, int out_size)
{
    const float* enc    = (const float*)d_in[0];
    const int*   word   = (const int*)  d_in[1];
    const float* lastc  = (const float*)d_in[2];
    const float* h0     = (const float*)d_in[3];
    const float* c0     = (const float*)d_in[4];
    const float* emb    = (const float*)d_in[5];
    const float* W_ih   = (const float*)d_in[6];
    const float* b_ih   = (const float*)d_in[7];
    const float* W_hh   = (const float*)d_in[8];
    const float* b_hh   = (const float*)d_in[9];
    const float* W_att  = (const float*)d_in[10];
    const float* b_att  = (const float*)d_in[11];
    const float* v      = (const float*)d_in[12];
    const float* W_ah   = (const float*)d_in[13];
    const float* b_ah   = (const float*)d_in[14];
    const float* W_out  = (const float*)d_in[15];
    const float* b_out  = (const float*)d_in[16];
    float* out = (float*)d_out;

    // flattened pytree: [output(V), h(H), c(H), x_t(H), w(S)]
    bool full = (out_size >= V_DIM + 3 * H_DIM + S_LEN);
    float* out_h  = full ? out + V_DIM              : nullptr;
    float* out_c  = full ? out + V_DIM + H_DIM      : nullptr;
    float* out_xt = full ? out + V_DIM + 2 * H_DIM  : nullptr;
    float* out_w  = full ? out + V_DIM + 3 * H_DIM  : nullptr;

    decoder_kernel<<<NBLK, NTHR>>>(enc, word, lastc, h0, c0, emb,
                                   W_ih, b_ih, W_hh, b_hh,
                                   W_att, b_att, v, W_ah, b_ah,
                                   W_out, b_out,
                                   out, out_h, out_c, out_xt, out_w);
}

// round 10
// speedup vs baseline: 1.0835x; 1.0835x over previous
#include <cuda_runtime.h>
#include <math.h>
#include <stdint.h>

#define S_LEN 2048
#define E_DIM 1024
#define H_DIM 1024
#define V_DIM 32000
#define EH    2048   // E+H

#define SC_BLOCKS 128      // scores kernel grid (1 CTA/SM, co-resident)
#define CT_BLOCKS 512      // context grid (<=4/SM, co-resident)
#define LG_BLOCKS 592      // logits grid (4/SM exactly, co-resident)

// ---------------- scratch (no allocations allowed) ----------------
__device__ __align__(16) float d_gates[4 * H_DIM];
__device__ __align__(16) float d_h[H_DIM];
__device__ __align__(16) float d_t[H_DIM];
__device__ __align__(16) float d_scores[S_LEN];
__device__ __align__(16) float d_ctx[E_DIM];
__device__ __align__(16) float d_xt[H_DIM];
__device__ __align__(16) float d_logits[V_DIM];
__device__ float d_sumexp;
__device__ float d_smax, d_sinv;
__device__ unsigned d_statcnt;                 // scores stats ticket
__device__ unsigned d_bar2, d_exit2;           // scores gridbar
__device__ unsigned d_bar3, d_exit3;           // context gridbar
__device__ unsigned d_bar4, d_exit4;           // logits gridbar

__device__ __forceinline__ float sigmoidf(float x) { return 1.0f / (1.0f + expf(-x)); }

__device__ __forceinline__ uint32_t f2tf32(float x) {
    uint32_t u;
    asm("cvt.rna.tf32.f32 %0, %1;" : "=r"(u) : "f"(x));
    return u;
}

__device__ __forceinline__ void mma_tf32(float* c, const uint32_t* a, const uint32_t* b) {
    asm volatile(
        "mma.sync.aligned.m16n8k8.row.col.f32.tf32.tf32.f32 "
        "{%0,%1,%2,%3}, {%4,%5,%6,%7}, {%8,%9}, {%0,%1,%2,%3};"
        : "+f"(c[0]), "+f"(c[1]), "+f"(c[2]), "+f"(c[3])
        : "r"(a[0]), "r"(a[1]), "r"(a[2]), "r"(a[3]), "r"(b[0]), "r"(b[1]));
}

// grid barrier over a co-resident grid. Counter is reset by the kernel's exit ticket.
__device__ __forceinline__ void gridbar(unsigned* cnt, unsigned target) {
    __syncthreads();
    if (threadIdx.x == 0) {
        __threadfence();
        atomicAdd(cnt, 1u);
        while (*(volatile unsigned*)cnt < target) { }
        __threadfence();
    }
    __syncthreads();
}

__device__ __forceinline__ void exit_ticket(unsigned* bar, unsigned* ex, unsigned nblk) {
    __syncthreads();
    if (threadIdx.x == 0) {
        __threadfence();
        if (atomicAdd(ex, 1u) == nblk - 1) {
            *bar = 0u; *ex = 0u;
            __threadfence();
        }
    }
}

// ---------------- K1: gate rows -> d_gates[4096] ----------------
__global__ void gates_kernel(const int* __restrict__ word_input,
                             const float* __restrict__ last_ctx,
                             const float* __restrict__ h0,
                             const float* __restrict__ emb,
                             const float* __restrict__ W_ih,
                             const float* __restrict__ b_ih,
                             const float* __restrict__ W_hh,
                             const float* __restrict__ b_hh)
{
    __shared__ float sin_[EH + H_DIM];
    int tid = threadIdx.x;
    int word = word_input[0];
    for (int i = tid; i < H_DIM; i += blockDim.x) {
        sin_[i]          = last_ctx[i];
        sin_[H_DIM + i]  = emb[(size_t)word * E_DIM + i];
        sin_[EH + i]     = h0[i];
    }
    __syncthreads();

    int r = blockIdx.x * 8 + (tid >> 5);
    int lane = tid & 31;

    const float* wrow = W_ih + (size_t)r * EH;
    float acc = 0.f;
    #pragma unroll
    for (int k = lane * 4; k < EH; k += 128) {
        float4 w = *(const float4*)&wrow[k];
        float4 x = *(const float4*)&sin_[k];
        acc += w.x*x.x + w.y*x.y + w.z*x.z + w.w*x.w;
    }
    const float* hrow = W_hh + (size_t)r * H_DIM;
    #pragma unroll
    for (int k = lane * 4; k < H_DIM; k += 128) {
        float4 w = *(const float4*)&hrow[k];
        float4 x = *(const float4*)&sin_[EH + k];
        acc += w.x*x.x + w.y*x.y + w.z*x.z + w.w*x.w;
    }
    #pragma unroll
    for (int off = 16; off; off >>= 1) acc += __shfl_down_sync(0xffffffffu, acc, off);
    if (lane == 0) d_gates[r] = acc + b_ih[r] + b_hh[r];
}

// ---------------- K2: h/c + t-rows + scores GEMM + softmax stats ----------------
// 128 blocks x 256 thr, 1 CTA/SM (heavy smem) -> co-resident, gridbar safe.
#define SKP 36   // 32 + 4 pad

__global__ __launch_bounds__(256, 1)
void scores_kernel(const float* __restrict__ enc,
                   const float* __restrict__ W_att,
                   const float* __restrict__ b_att,
                   const float* __restrict__ c0,
                   const float* __restrict__ v,
                   float* out_h, float* out_c)
{
    __shared__ union {
        float sh[H_DIM];
        struct { uint32_t As[128][SKP]; uint32_t Bs[128][SKP]; } g;
    } smu;
    __shared__ float srow[2][128];
    __shared__ float red8[8];
    __shared__ bool amLast;

    const int tid  = threadIdx.x;
    const int blk  = blockIdx.x;
    const int warp = tid >> 5, lane = tid & 31;

    // ---- phase A: h/c from gates, zero scratch, t rows ----
    for (int j = tid; j < H_DIM; j += 256) {
        float iv = sigmoidf(d_gates[j]);
        float fv = sigmoidf(d_gates[j +   H_DIM]);
        float gv = tanhf  (d_gates[j + 2*H_DIM]);
        float ov = sigmoidf(d_gates[j + 3*H_DIM]);
        float cv = fv * c0[j] + iv * gv;
        float hv = ov * tanhf(cv);
        smu.sh[j] = hv;
        if (blk == 0) {
            d_h[j] = hv;
            if (out_h) out_h[j] = hv;
            if (out_c) out_c[j] = cv;
        }
    }
    if (blk == 1) {
        for (int i = tid; i < S_LEN; i += 256) d_scores[i] = 0.f;
        if (tid == 0) { d_statcnt = 0u; d_sumexp = 0.f; }
    }
    if (blk == 2) for (int i = tid; i < E_DIM; i += 256) d_ctx[i] = 0.f;
    __syncthreads();

    {   // t[r] = W_att[r, :H] . h + b_att[r]; 8 rows per block
        int r = blk * 8 + warp;
        const float* row = W_att + (size_t)r * EH;
        float acc = 0.f;
        #pragma unroll
        for (int k = lane * 4; k < H_DIM; k += 128) {
            float4 w = *(const float4*)&row[k];
            float4 x = *(const float4*)&smu.sh[k];
            acc += w.x*x.x + w.y*x.y + w.z*x.z + w.w*x.w;
        }
        #pragma unroll
        for (int off = 16; off; off >>= 1) acc += __shfl_down_sync(0xffffffffu, acc, off);
        if (lane == 0) d_t[r] = acc + b_att[r];
    }
    gridbar(&d_bar2, SC_BLOCKS);

    // ---- phase B: 128x128 GEMM tile, tf32 mma (R8 layout) ----
    const int m0 = (blk >> 3) * 128;   // 16 m-tiles
    const int n0 = (blk & 7) * 128;    // 8 n-tiles
    const int g = lane >> 2, tg = lane & 3;
    const int wm = (warp >> 1) * 32;
    const int wn = (warp & 1) * 64;

    float c[2][8][4];
    #pragma unroll
    for (int mt = 0; mt < 2; mt++)
        #pragma unroll
        for (int nt = 0; nt < 8; nt++)
            #pragma unroll
            for (int i = 0; i < 4; i++) c[mt][nt][i] = 0.f;

    const int lrow = tid >> 3;          // 0..31
    const int lcol = (tid & 7) * 4;     // 0..28

    const float* aptr = enc   + (size_t)(m0 + lrow) * E_DIM + lcol;
    const float* bptr = W_att + (size_t)(n0 + lrow) * EH + H_DIM + lcol;

    float4 ra[4], rb[4];
    #pragma unroll
    for (int i = 0; i < 4; i++) ra[i] = *(const float4*)(aptr + (size_t)i * 32 * E_DIM);
    #pragma unroll
    for (int i = 0; i < 4; i++) rb[i] = *(const float4*)(bptr + (size_t)i * 32 * EH);

    for (int kt = 0; kt < E_DIM / 32; kt++) {
        #pragma unroll
        for (int i = 0; i < 4; i++) {
            int r = lrow + i * 32;
            smu.g.As[r][lcol + 0] = f2tf32(ra[i].x);
            smu.g.As[r][lcol + 1] = f2tf32(ra[i].y);
            smu.g.As[r][lcol + 2] = f2tf32(ra[i].z);
            smu.g.As[r][lcol + 3] = f2tf32(ra[i].w);
            smu.g.Bs[r][lcol + 0] = f2tf32(rb[i].x);
            smu.g.Bs[r][lcol + 1] = f2tf32(rb[i].y);
            smu.g.Bs[r][lcol + 2] = f2tf32(rb[i].z);
            smu.g.Bs[r][lcol + 3] = f2tf32(rb[i].w);
        }
        __syncthreads();

        if (kt + 1 < E_DIM / 32) {
            const float* an = aptr + (size_t)(kt + 1) * 32;
            const float* bn = bptr + (size_t)(kt + 1) * 32;
            #pragma unroll
            for (int i = 0; i < 4; i++) ra[i] = *(const float4*)(an + (size_t)i * 32 * E_DIM);
            #pragma unroll
            for (int i = 0; i < 4; i++) rb[i] = *(const float4*)(bn + (size_t)i * 32 * EH);
        }

        #pragma unroll
        for (int ks = 0; ks < 4; ks++) {
            int k0 = ks * 8;
            uint32_t a[2][4], b[8][2];
            #pragma unroll
            for (int mt = 0; mt < 2; mt++) {
                int r = wm + mt * 16 + g;
                a[mt][0] = smu.g.As[r    ][k0 + tg    ];
                a[mt][1] = smu.g.As[r + 8][k0 + tg    ];
                a[mt][2] = smu.g.As[r    ][k0 + tg + 4];
                a[mt][3] = smu.g.As[r + 8][k0 + tg + 4];
            }
            #pragma unroll
            for (int nt = 0; nt < 8; nt++) {
                int r = wn + nt * 8 + g;
                b[nt][0] = smu.g.Bs[r][k0 + tg    ];
                b[nt][1] = smu.g.Bs[r][k0 + tg + 4];
            }
            #pragma unroll
            for (int mt = 0; mt < 2; mt++)
                #pragma unroll
                for (int nt = 0; nt < 8; nt++)
                    mma_tf32(c[mt][nt], a[mt], b[nt]);
        }
        __syncthreads();
    }

    // epilogue: v . tanh(acc + t), atomic into d_scores
    #pragma unroll
    for (int mt = 0; mt < 2; mt++) {
        float p0 = 0.f, p1 = 0.f;
        #pragma unroll
        for (int nt = 0; nt < 8; nt++) {
            #pragma unroll
            for (int cc = 0; cc < 2; cc++) {
                int n = n0 + wn + nt * 8 + tg * 2 + cc;
                float tn = d_t[n];
                float vn = v[n];
                p0 += vn * tanhf(c[mt][nt][cc]     + tn);
                p1 += vn * tanhf(c[mt][nt][2 + cc] + tn);
            }
        }
        p0 += __shfl_xor_sync(0xffffffffu, p0, 1);
        p0 += __shfl_xor_sync(0xffffffffu, p0, 2);
        p1 += __shfl_xor_sync(0xffffffffu, p1, 1);
        p1 += __shfl_xor_sync(0xffffffffu, p1, 2);
        if (tg == 0) {
            srow[warp & 1][wm + mt * 16 + g    ] = p0;
            srow[warp & 1][wm + mt * 16 + g + 8] = p1;
        }
    }
    __syncthreads();
    if (tid < 128)
        atomicAdd(&d_scores[m0 + tid], srow[0][tid] + srow[1][tid]);

    // last block computes softmax stats
    __threadfence();
    __syncthreads();
    if (tid == 0) amLast = (atomicAdd(&d_statcnt, 1u) == SC_BLOCKS - 1);
    __syncthreads();
    if (amLast) {
        float m = -1e30f;
        #pragma unroll
        for (int i = tid; i < S_LEN; i += 256) m = fmaxf(m, d_scores[i]);
        #pragma unroll
        for (int off = 16; off; off >>= 1) m = fmaxf(m, __shfl_xor_sync(0xffffffffu, m, off));
        if (lane == 0) red8[warp] = m;
        __syncthreads();
        float mx;
        {
            float t0 = red8[0];
            #pragma unroll
            for (int i = 1; i < 8; i++) t0 = fmaxf(t0, red8[i]);
            mx = t0;
        }
        float sum = 0.f;
        #pragma unroll
        for (int i = tid; i < S_LEN; i += 256) sum += expf(d_scores[i] - mx);
        #pragma unroll
        for (int off = 16; off; off >>= 1) sum += __shfl_xor_sync(0xffffffffu, sum, off);
        __syncthreads();
        if (lane == 0) red8[warp] = sum;
        __syncthreads();
        if (tid == 0) {
            float s = red8[0];
            #pragma unroll
            for (int i = 1; i < 8; i++) s += red8[i];
            d_smax = mx;
            d_sinv = 1.0f / s;
        }
    }
    exit_ticket(&d_bar2, &d_exit2, SC_BLOCKS);
}

// ---------------- K3: context + xt ----------------
// grid (128,4) = 512 blocks, <=4/SM with launch_bounds(256,4) -> co-resident.
__global__ __launch_bounds__(256, 4)
void context_kernel(const float* __restrict__ enc,
                    const float* __restrict__ W_ah,
                    const float* __restrict__ b_ah,
                    float* out_w, float* out_xt)
{
    __shared__ float sw[16];
    int tid = threadIdx.x;
    int warp = tid >> 5, lane = tid & 31;
    float mx = d_smax, inv = d_sinv;

    int s0 = blockIdx.x * 16;
    if (tid < 16) {
        float w = expf(d_scores[s0 + tid] - mx) * inv;
        sw[tid] = w;
        if (blockIdx.y == 0 && out_w) out_w[s0 + tid] = w;
    }
    __syncthreads();

    int e = blockIdx.y * 256 + tid;
    float a0 = 0.f, a1 = 0.f, a2 = 0.f, a3 = 0.f;
    #pragma unroll
    for (int s = 0; s < 16; s += 4) {
        a0 += sw[s    ] * enc[(size_t)(s0 + s    ) * E_DIM + e];
        a1 += sw[s + 1] * enc[(size_t)(s0 + s + 1) * E_DIM + e];
        a2 += sw[s + 2] * enc[(size_t)(s0 + s + 2) * E_DIM + e];
        a3 += sw[s + 3] * enc[(size_t)(s0 + s + 3) * E_DIM + e];
    }
    atomicAdd(&d_ctx[e], (a0 + a1) + (a2 + a3));

    gridbar(&d_bar3, CT_BLOCKS);

    // xt tail: 2 rows per block (warps 0,1)
    if (warp < 2) {
        int bid = blockIdx.y * 128 + blockIdx.x;
        int r = bid * 2 + warp;
        const float* row = W_ah + (size_t)r * EH;
        float acc = 0.f;
        #pragma unroll
        for (int k = lane * 4; k < H_DIM; k += 128) {
            float4 w = *(const float4*)&row[k];
            float4 x = *(const float4*)&d_ctx[k];
            acc += w.x*x.x + w.y*x.y + w.z*x.z + w.w*x.w;
        }
        #pragma unroll
        for (int k = lane * 4; k < H_DIM; k += 128) {
            float4 w = *(const float4*)&row[H_DIM + k];
            float4 x = *(const float4*)&d_h[k];
            acc += w.x*x.x + w.y*x.y + w.z*x.z + w.w*x.w;
        }
        #pragma unroll
        for (int off = 16; off; off >>= 1) acc += __shfl_down_sync(0xffffffffu, acc, off);
        if (lane == 0) {
            float x = tanhf(acc + b_ah[r]);
            d_xt[r] = x;
            if (out_xt) out_xt[r] = x;
        }
    }
    exit_ticket(&d_bar3, &d_exit3, CT_BLOCKS);
}

// ---------------- K4: logits + sumexp + writeout ----------------
// 592 blocks x 256 thr = 4 CTAs/SM exactly -> co-resident.
__global__ __launch_bounds__(256, 4)
void logits_kernel(const float* __restrict__ W_out,
                   const float* __restrict__ b_out,
                   float* __restrict__ out)
{
    __shared__ float sx[H_DIM];
    __shared__ float wexp[8];
    int tid = threadIdx.x;
    int blk = blockIdx.x;
    int warp = tid >> 5, lane = tid & 31;

    for (int i = tid; i < H_DIM; i += 256) sx[i] = d_xt[i];
    __syncthreads();

    float esum = 0.f;
    for (int r = blk * 8 + warp; r < V_DIM; r += LG_BLOCKS * 8) {
        const float* wr = W_out + (size_t)r * H_DIM;
        float acc = 0.f;
        #pragma unroll
        for (int k = lane * 4; k < H_DIM; k += 128) {
            float4 w = *(const float4*)&wr[k];
            float4 x = *(const float4*)&sx[k];
            acc += w.x*x.x + w.y*x.y + w.z*x.z + w.w*x.w;
        }
        #pragma unroll
        for (int off = 16; off; off >>= 1) acc += __shfl_down_sync(0xffffffffu, acc, off);
        if (lane == 0) {
            float lg = acc + b_out[r];
            d_logits[r] = lg;
            esum += expf(lg);     // logits are O(1): exp without max is safe
        }
    }
    if (lane == 0) wexp[warp] = esum;
    __syncthreads();
    if (tid == 0) {
        float s = wexp[0];
        #pragma unroll
        for (int i = 1; i < 8; i++) s += wexp[i];
        atomicAdd(&d_sumexp, s);
    }

    gridbar(&d_bar4, LG_BLOCKS);

    float lse = logf(d_sumexp);
    for (int i = blk * 256 + tid; i < V_DIM; i += LG_BLOCKS * 256)
        out[i] = d_logits[i] - lse;

    exit_ticket(&d_bar4, &d_exit4, LG_BLOCKS);
}

// ---------------- launch ----------------
extern "C" void kernel_launch(void* const* d_in, const int* in_sizes, int n_in,
                              void* d_out, int out_size)
{
    const float* enc    = (const float*)d_in[0];
    const int*   word   = (const int*)  d_in[1];
    const float* lastc  = (const float*)d_in[2];
    const float* h0     = (const float*)d_in[3];
    const float* c0     = (const float*)d_in[4];
    const float* emb    = (const float*)d_in[5];
    const float* W_ih   = (const float*)d_in[6];
    const float* b_ih   = (const float*)d_in[7];
    const float* W_hh   = (const float*)d_in[8];
    const float* b_hh   = (const float*)d_in[9];
    const float* W_att  = (const float*)d_in[10];
    const float* b_att  = (const float*)d_in[11];
    const float* v      = (const float*)d_in[12];
    const float* W_ah   = (const float*)d_in[13];
    const float* b_ah   = (const float*)d_in[14];
    const float* W_out  = (const float*)d_in[15];
    const float* b_out  = (const float*)d_in[16];
    float* out = (float*)d_out;

    // flattened pytree: [output(V), h(H), c(H), x_t(H), w(S)]
    bool full = (out_size >= V_DIM + 3 * H_DIM + S_LEN);
    float* out_h  = full ? out + V_DIM              : nullptr;
    float* out_c  = full ? out + V_DIM + H_DIM      : nullptr;
    float* out_xt = full ? out + V_DIM + 2 * H_DIM  : nullptr;
    float* out_w  = full ? out + V_DIM + 3 * H_DIM  : nullptr;

    gates_kernel  <<<512, 256>>>(word, lastc, h0, emb, W_ih, b_ih, W_hh, b_hh);
    scores_kernel <<<SC_BLOCKS, 256>>>(enc, W_att, b_att, c0, v, out_h, out_c);
    context_kernel<<<dim3(128, 4), 256>>>(enc, W_ah, b_ah, out_w, out_xt);
    logits_kernel <<<LG_BLOCKS, 256>>>(W_out, b_out, out);
}